// round 5
// baseline (speedup 1.0000x reference)
#include <cuda_runtime.h>
#include <math.h>

#define B_ 8
#define N_ 256
#define F_ 59
#define C_ 128
#define G_ 8            // receivers per main block
#define MAXROWS 640     // multiple of 64
#define LOG2E 1.4426950408889634f

// ---------------- device scratch ----------------
__device__ float g_v[B_*N_*C_];
__device__ float g_tsrc[B_*N_*C_];
__device__ float g_tdst[B_*N_*C_];
__device__ float g_awfT[C_*C_];   // folded attn_w (x log2e) transposed: [c][d]

// ---------------- packed f32x2 helpers ----------------
__device__ __forceinline__ unsigned long long dup2(float x) {
    unsigned long long r;
    asm("mov.b64 %0, {%1, %1};" : "=l"(r) : "r"(__float_as_uint(x)));
    return r;
}
__device__ __forceinline__ void fma2(unsigned long long& a,
                                     unsigned long long x, unsigned long long y) {
    asm("fma.rn.f32x2 %0, %1, %2, %0;" : "+l"(a) : "l"(x), "l"(y));
}

// =====================================================================
// Kernel 1: per-node precompute (+ inline BN fold of attn_w * log2e)
// grid = 128 (16 nodes each), block = 256
// =====================================================================
__global__ void __launch_bounds__(256, 1)
precompute_kernel(const float* __restrict__ x,
                  const float* __restrict__ Wl,
                  const float* __restrict__ Ws,
                  const float* __restrict__ Wd,
                  const float* __restrict__ attn_w, const float* __restrict__ attn_b,
                  const float* __restrict__ ag, const float* __restrict__ ab,
                  const float* __restrict__ am, const float* __restrict__ av)
{
    extern __shared__ float sh[];
    float* s_wl = sh;                  // [128][60]
    float* s_ws = s_wl + 128*60;
    float* s_wd = s_ws + 128*60;
    float* s_aw = s_wd + 128*60;       // [128][132] folded (x log2e)
    float* s_x  = s_aw + 128*132;      // [16][64]
    float* s_as = s_x  + 16*64;        // [16][128]
    float* s_ad = s_as + 16*128;       // [16][128]
    float* s_s2 = s_ad + 16*128;       // [128]
    float* s_b2 = s_s2 + 128;          // [128]

    const int t   = threadIdx.x;
    const int blk = blockIdx.x;        // node base = blk*16

    if (t < 128) {
        float s2 = ag[t] * rsqrtf(av[t] + 1e-5f);
        s_b2[t] = (attn_b[t] * s2 + ab[t] - am[t] * s2) * LOG2E;
        s_s2[t] = s2 * LOG2E;
    }
    __syncthreads();

    for (int idx = t; idx < 128*F_; idx += 256) {
        int c = idx / F_, f = idx % F_;
        s_wl[c*60 + f] = Wl[idx];
        s_ws[c*60 + f] = Ws[idx];
        s_wd[c*60 + f] = Wd[idx];
    }
    {
        const float4* aw4 = (const float4*)attn_w;
        for (int i4 = t; i4 < C_*C_/4; i4 += 256) {
            float4 w = aw4[i4];
            int c = i4 >> 5, k = (i4 & 31) * 4;
            float s2 = s_s2[c];
            float* dst = s_aw + c*132 + k;
            dst[0] = w.x*s2; dst[1] = w.y*s2; dst[2] = w.z*s2; dst[3] = w.w*s2;
        }
    }
    for (int idx = t; idx < 16*F_; idx += 256) {
        int n = idx / F_, f = idx % F_;
        s_x[n*64 + f] = x[blk*16*F_ + idx];
    }
    __syncthreads();

    // export this block's awfT column slice (c = blk)
    if (t < 128) g_awfT[t*C_ + blk] = s_aw[blk*132 + t];

    const int c = t & 127, g = t >> 7;

    float accv[8], accs[8], accd[8];
#pragma unroll
    for (int n = 0; n < 8; n++) { accv[n] = 0.f; accs[n] = 0.f; accd[n] = 0.f; }

    for (int f4 = 0; f4 < 56; f4 += 4) {
        float4 wl4 = *(const float4*)(s_wl + c*60 + f4);
        float4 ws4 = *(const float4*)(s_ws + c*60 + f4);
        float4 wd4 = *(const float4*)(s_wd + c*60 + f4);
#pragma unroll
        for (int n = 0; n < 8; n++) {
            float4 x4 = *(const float4*)(s_x + (g*8 + n)*64 + f4);
            accv[n] = fmaf(x4.x, wl4.x, fmaf(x4.y, wl4.y, fmaf(x4.z, wl4.z, fmaf(x4.w, wl4.w, accv[n]))));
            accs[n] = fmaf(x4.x, ws4.x, fmaf(x4.y, ws4.y, fmaf(x4.z, ws4.z, fmaf(x4.w, ws4.w, accs[n]))));
            accd[n] = fmaf(x4.x, wd4.x, fmaf(x4.y, wd4.y, fmaf(x4.z, wd4.z, fmaf(x4.w, wd4.w, accd[n]))));
        }
    }
#pragma unroll
    for (int f = 56; f < F_; f++) {
        float wl = s_wl[c*60 + f], ws = s_ws[c*60 + f], wd = s_wd[c*60 + f];
#pragma unroll
        for (int n = 0; n < 8; n++) {
            float xv = s_x[(g*8 + n)*64 + f];
            accv[n] = fmaf(xv, wl, accv[n]);
            accs[n] = fmaf(xv, ws, accs[n]);
            accd[n] = fmaf(xv, wd, accd[n]);
        }
    }
#pragma unroll
    for (int n = 0; n < 8; n++) {
        int node = g*8 + n;
        g_v[(blk*16 + node)*C_ + c] = accv[n];
        s_as[node*128 + c] = accs[n];
        s_ad[node*128 + c] = accd[n];
    }
    __syncthreads();

    float ts[8], td[8];
#pragma unroll
    for (int n = 0; n < 8; n++) { ts[n] = 0.f; td[n] = 0.f; }

    for (int k4 = 0; k4 < C_; k4 += 4) {
        float4 aw4 = *(const float4*)(s_aw + c*132 + k4);
#pragma unroll
        for (int n = 0; n < 8; n++) {
            float4 a4 = *(const float4*)(s_as + (g*8 + n)*128 + k4);
            float4 d4 = *(const float4*)(s_ad + (g*8 + n)*128 + k4);
            ts[n] = fmaf(a4.x, aw4.x, fmaf(a4.y, aw4.y, fmaf(a4.z, aw4.z, fmaf(a4.w, aw4.w, ts[n]))));
            td[n] = fmaf(d4.x, aw4.x, fmaf(d4.y, aw4.y, fmaf(d4.z, aw4.z, fmaf(d4.w, aw4.w, td[n]))));
        }
    }
    float b2 = s_b2[c];
#pragma unroll
    for (int n = 0; n < 8; n++) {
        int node = g*8 + n;
        g_tsrc[(blk*16 + node)*C_ + c] = ts[n];
        g_tdst[(blk*16 + node)*C_ + c] = td[n] + b2;
    }
}

// =====================================================================
// Kernel 2: fused attention. grid = 256 (8 receivers), block = 256,
// 64-row tiles, 8d x 4row register blocking, merged gather-epilogue.
// =====================================================================
__global__ void __launch_bounds__(256, 2)
main_kernel(const float* __restrict__ pos, const float* __restrict__ nrm,
            const float* __restrict__ rptr,
            const float* __restrict__ pos_w, const float* __restrict__ pos_b,
            const float* __restrict__ pg, const float* __restrict__ pb,
            const float* __restrict__ pm, const float* __restrict__ pv,
            float* __restrict__ out)
{
    extern __shared__ float sh[];
    float* s_awt  = sh;                     // [c][d]       16384
    float* s_dt   = s_awt + C_*C_;          // [c][64 rows]  8192
    float* s_sc   = s_dt;                   // [row][d] alias 8192
    float* s_relf = s_dt + C_*64;           // [64][9]        576
    float* s_pw   = s_relf + 64*9;          // [128][6]       768
    float* s_pb   = s_pw + C_*6;            //                128
    float* s_td   = s_pb + C_;              // [ii][d]       1024
    float* s_posn = s_td + G_*C_;           // [j][3]         768
    float* s_geo  = s_posn + 256*3;         // [ii][6]         48
    int*   s_rows = (int*)(s_geo + G_*6);   // MAXROWS
    int*   s_mask = s_rows + MAXROWS;       // [8][8]
    int*   s_woff = s_mask + 64;            // [8][8]
    int*   s_roff = s_woff + 64;            // [9]

    const int blk = blockIdx.x;
    const int b  = blk >> 5;
    const int i0 = (blk & 31) * G_;
    const int t  = threadIdx.x;
    const int wd = t >> 5, ln = t & 31;

    // ---- stage constants ----
    {
        const float4* src = (const float4*)g_awfT;
        float4* dst = (float4*)s_awt;
        for (int i4 = t; i4 < C_*C_/4; i4 += 256) dst[i4] = src[i4];
    }
    if (t < C_) {   // fold pos_nn BN inline
        float s1 = pg[t] * rsqrtf(pv[t] + 1e-5f);
        s_pb[t] = pos_b[t] * s1 + pb[t] - pm[t] * s1;
#pragma unroll
        for (int k = 0; k < 6; k++) s_pw[t*6 + k] = pos_w[t*6 + k] * s1;
    }
    for (int idx = t; idx < G_*C_; idx += 256) {
        int ii = idx >> 7, dd = idx & 127;
        s_td[idx] = g_tdst[(b*N_ + i0 + ii)*C_ + dd];
    }
    {
        const float* pj = pos + (b*N_ + t)*3;
        s_posn[t*3+0] = pj[0]; s_posn[t*3+1] = pj[1]; s_posn[t*3+2] = pj[2];
    }
    if (t < G_*6) {
        int ii = t / 6, k = t % 6;
        s_geo[t] = (k < 3) ? pos[(b*N_ + i0 + ii)*3 + k]
                           : nrm[(b*N_ + i0 + ii)*3 + (k - 3)];
    }
    __syncthreads();

    float rr;
    { int iv = *(const int*)rptr; rr = (iv > 0 && iv < 1000000) ? (float)iv : *rptr; }
    const float r2 = rr * rr;

    // ---- deterministic sorted compaction ----
    unsigned predbits = 0;
    {
        float px = s_posn[t*3+0], py = s_posn[t*3+1], pz = s_posn[t*3+2];
#pragma unroll
        for (int ii = 0; ii < G_; ii++) {
            float dx = s_geo[ii*6+0] - px;
            float dy = s_geo[ii*6+1] - py;
            float dz = s_geo[ii*6+2] - pz;
            if (dx*dx + dy*dy + dz*dz <= r2) predbits |= (1u << ii);
        }
    }
#pragma unroll
    for (int ii = 0; ii < G_; ii++) {
        unsigned msk = __ballot_sync(0xFFFFFFFFu, (predbits >> ii) & 1u);
        if (ln == 0) s_mask[ii*8 + wd] = (int)msk;
    }
    __syncthreads();

    if (t < 32) {
        int ii = ln;
        int cnt = 0;
        if (ii < 8)
            for (int w = 0; w < 8; w++) cnt += __popc((unsigned)s_mask[ii*8 + w]);
        int incl = cnt;
#pragma unroll
        for (int off = 1; off < 8; off <<= 1) {
            int v = __shfl_up_sync(0xFFFFFFFFu, incl, off);
            if (ln >= off) incl += v;
        }
        if (ii < 8) {
            int excl = incl - cnt;
            s_roff[ii] = excl < MAXROWS ? excl : MAXROWS;
            int run = excl;
            for (int w = 0; w < 8; w++) {
                s_woff[ii*8 + w] = run;
                run += __popc((unsigned)s_mask[ii*8 + w]);
            }
            if (ii == 7) s_roff[8] = run < MAXROWS ? run : MAXROWS;
        }
    }
    __syncthreads();

#pragma unroll
    for (int ii = 0; ii < G_; ii++) {
        if ((predbits >> ii) & 1u) {
            unsigned msk = (unsigned)s_mask[ii*8 + wd];
            int idx = s_woff[ii*8 + wd] + __popc(msk & ((1u << ln) - 1u));
            if (idx < MAXROWS) s_rows[idx] = t | (ii << 8);
        }
    }
    __syncthreads();
    const int nrows = s_roff[8];
    const int T = (nrows + 63) & ~63;
    if (t < T - nrows) s_rows[nrows + t] = 0;   // benign padding
    __syncthreads();

    // roles
    const int d  = t & 127, q  = t >> 7;   // epilogue: channel, receiver-half
    const int dg = t & 15,  rg = t >> 4;   // matvec: d-group(8), row-group(4)
    const int d0 = dg*8,    r0 = rg*4;

    float pwd[6];
#pragma unroll
    for (int k = 0; k < 6; k++) pwd[k] = s_pw[d*6 + k];
    const float pbd = s_pb[d];
    const float* tsb = g_tsrc + (size_t)(b*N_)*C_;
    const float* vb  = g_v    + (size_t)(b*N_)*C_;

    float l_[4], o_[4];
#pragma unroll
    for (int s = 0; s < 4; s++) { l_[s] = 0.f; o_[s] = 0.f; }

    for (int base = 0; base < T; base += 64) {
        // --- relative geometry for 64 rows ---
        if (t < 64) {
            int tag = s_rows[base + t];
            int j = tag & 255, ii = tag >> 8;
            const float* nj = nrm + (b*N_ + j)*3;
            float* rf = s_relf + t*9;
            rf[0] = s_geo[ii*6+0] - s_posn[j*3+0];
            rf[1] = s_geo[ii*6+1] - s_posn[j*3+1];
            rf[2] = s_geo[ii*6+2] - s_posn[j*3+2];
            rf[3] = s_geo[ii*6+3] - nj[0];
            rf[4] = s_geo[ii*6+4] - nj[1];
            rf[5] = s_geo[ii*6+5] - nj[2];
        }
        __syncthreads();

        // --- delta fill: s_dt[c][row], row = t&63, c-chunk = t>>6 ---
        {
            int row = t & 63, cg = t >> 6;
            float rf[6];
#pragma unroll
            for (int k = 0; k < 6; k++) rf[k] = s_relf[row*9 + k];
#pragma unroll
            for (int cc = 0; cc < 32; cc++) {
                int c = cg*32 + cc;
                float dv = s_pb[c];
#pragma unroll
                for (int k = 0; k < 6; k++) dv = fmaf(rf[k], s_pw[c*6 + k], dv);
                s_dt[c*64 + row] = fmaxf(dv, 0.f);
            }
        }
        __syncthreads();

        // --- matvec: 8 d x 4 rows per thread, packed over d ---
        unsigned long long acc[4][4];
#pragma unroll
        for (int r = 0; r < 4; r++)
#pragma unroll
            for (int p = 0; p < 4; p++) acc[r][p] = 0ULL;

#pragma unroll 2
        for (int c = 0; c < C_; c++) {
            ulonglong2 wa = *(const ulonglong2*)(s_awt + c*C_ + d0);      // d0..d0+3
            ulonglong2 wb = *(const ulonglong2*)(s_awt + c*C_ + d0 + 4);  // d0+4..d0+7
            float4 rv = *(const float4*)(s_dt + c*64 + r0);               // 4 rows
            unsigned long long b0 = dup2(rv.x), b1 = dup2(rv.y);
            unsigned long long b2v = dup2(rv.z), b3 = dup2(rv.w);
            fma2(acc[0][0], wa.x, b0);  fma2(acc[0][1], wa.y, b0);
            fma2(acc[0][2], wb.x, b0);  fma2(acc[0][3], wb.y, b0);
            fma2(acc[1][0], wa.x, b1);  fma2(acc[1][1], wa.y, b1);
            fma2(acc[1][2], wb.x, b1);  fma2(acc[1][3], wb.y, b1);
            fma2(acc[2][0], wa.x, b2v); fma2(acc[2][1], wa.y, b2v);
            fma2(acc[2][2], wb.x, b2v); fma2(acc[2][3], wb.y, b2v);
            fma2(acc[3][0], wa.x, b3);  fma2(acc[3][1], wa.y, b3);
            fma2(acc[3][2], wb.x, b3);  fma2(acc[3][3], wb.y, b3);
        }
        __syncthreads();   // all s_dt reads done before s_sc overwrite (alias)

#pragma unroll
        for (int r = 0; r < 4; r++) {
#pragma unroll
            for (int p = 0; p < 4; p++)
                *(unsigned long long*)(s_sc + (r0 + r)*C_ + d0 + 2*p) = acc[r][p];
        }
        __syncthreads();

        // --- merged epilogue: gather + exp2 softmax accumulation ---
#pragma unroll
        for (int s = 0; s < 4; s++) {
            int ii = q*4 + s;
            int lo = s_roff[ii]   - base; if (lo < 0)  lo = 0;
            int hi = s_roff[ii+1] - base; if (hi > 64) hi = 64;
            const float* tdp = s_td + ii*C_;
#pragma unroll 2
            for (int r = lo; r < hi; r++) {
                int j = s_rows[base + r] & 255;
                float tsv = tsb[j*C_ + d];
                float vvv = vb[j*C_ + d];
                float z = s_sc[r*C_ + d] + tdp[d] - tsv;
                float sv = fmaxf(z, 0.f);
                float e = exp2f(sv);
                float dv = pbd;
#pragma unroll
                for (int kk = 0; kk < 6; kk++)
                    dv = fmaf(s_relf[r*9 + kk], pwd[kk], dv);
                dv = fmaxf(dv, 0.f);
                l_[s] += e;
                o_[s] = fmaf(e, vvv + dv, o_[s]);
            }
        }
        __syncthreads();
    }

#pragma unroll
    for (int s = 0; s < 4; s++) {
        int ii = q*4 + s;
        out[(b*N_ + i0 + ii)*C_ + d] = o_[s] / l_[s];   // self-loop => l > 0
    }
}

// ---------------- launch ----------------
extern "C" void kernel_launch(void* const* d_in, const int* in_sizes, int n_in,
                              void* d_out, int out_size)
{
    const float* x      = (const float*)d_in[0];
    const float* pos    = (const float*)d_in[1];
    const float* normal = (const float*)d_in[2];
    const float* W_lin  = (const float*)d_in[3];
    const float* W_src  = (const float*)d_in[4];
    const float* W_dst  = (const float*)d_in[5];
    const float* pos_w  = (const float*)d_in[6];
    const float* pos_b  = (const float*)d_in[7];
    const float* pbn_g  = (const float*)d_in[8];
    const float* pbn_b  = (const float*)d_in[9];
    const float* pbn_m  = (const float*)d_in[10];
    const float* pbn_v  = (const float*)d_in[11];
    const float* attn_w = (const float*)d_in[12];
    const float* attn_b = (const float*)d_in[13];
    const float* abn_g  = (const float*)d_in[14];
    const float* abn_b  = (const float*)d_in[15];
    const float* abn_m  = (const float*)d_in[16];
    const float* abn_v  = (const float*)d_in[17];
    const float* rptr   = (const float*)d_in[18];
    float* out = (float*)d_out;

    const size_t smemB = (size_t)(3*128*60 + 128*132 + 16*64 + 2*16*128 + 256) * sizeof(float);
    const size_t smemC = (size_t)(C_*C_ + C_*64 + 64*9 + C_*6 + C_ + G_*C_ + 256*3 + G_*6) * sizeof(float)
                       + (size_t)(MAXROWS + 64 + 64 + 9) * sizeof(int);

    cudaFuncSetAttribute(precompute_kernel, cudaFuncAttributeMaxDynamicSharedMemorySize, (int)smemB);
    cudaFuncSetAttribute(main_kernel,       cudaFuncAttributeMaxDynamicSharedMemorySize, (int)smemC);
    (void)in_sizes; (void)n_in; (void)out_size;

    precompute_kernel<<<B_*N_/16, 256, smemB>>>(x, W_lin, W_src, W_dst,
                                                attn_w, attn_b, abn_g, abn_b, abn_m, abn_v);
    main_kernel<<<B_*N_/G_, 256, smemC>>>(pos, normal, rptr,
                                          pos_w, pos_b, pbn_g, pbn_b, pbn_m, pbn_v,
                                          out);
}

// round 6
// speedup vs baseline: 1.3074x; 1.3074x over previous
#include <cuda_runtime.h>
#include <math.h>

#define B_ 8
#define N_ 256
#define F_ 59
#define C_ 128
#define G_ 16           // receivers per main block
#define TILE 128        // rows per tile
#define MAXROWS 768     // multiple of TILE not required; clamped
#define LOG2E 1.4426950408889634f

// ---------------- device scratch ----------------
__device__ float g_v[B_*N_*C_];
__device__ float g_tsrc[B_*N_*C_];
__device__ float g_tdst[B_*N_*C_];
__device__ float g_awfT[C_*C_];   // folded attn_w (x log2e) transposed: [c][d]

// ---------------- packed f32x2 helpers ----------------
__device__ __forceinline__ unsigned long long dup2(float x) {
    unsigned long long r;
    asm("mov.b64 %0, {%1, %1};" : "=l"(r) : "r"(__float_as_uint(x)));
    return r;
}
__device__ __forceinline__ void fma2(unsigned long long& a,
                                     unsigned long long x, unsigned long long y) {
    asm("fma.rn.f32x2 %0, %1, %2, %0;" : "+l"(a) : "l"(x), "l"(y));
}

// =====================================================================
// Kernel 1: per-node precompute (+ inline BN fold of attn_w * log2e)
// grid = 128 (16 nodes each), block = 256
// =====================================================================
__global__ void __launch_bounds__(256, 1)
precompute_kernel(const float* __restrict__ x,
                  const float* __restrict__ Wl,
                  const float* __restrict__ Ws,
                  const float* __restrict__ Wd,
                  const float* __restrict__ attn_w, const float* __restrict__ attn_b,
                  const float* __restrict__ ag, const float* __restrict__ ab,
                  const float* __restrict__ am, const float* __restrict__ av)
{
    extern __shared__ float sh[];
    float* s_wl = sh;                  // [128][60]
    float* s_ws = s_wl + 128*60;
    float* s_wd = s_ws + 128*60;
    float* s_aw = s_wd + 128*60;       // [128][132] folded (x log2e)
    float* s_x  = s_aw + 128*132;      // [16][64]
    float* s_as = s_x  + 16*64;        // [16][128]
    float* s_ad = s_as + 16*128;       // [16][128]
    float* s_s2 = s_ad + 16*128;       // [128]
    float* s_b2 = s_s2 + 128;          // [128]

    const int t   = threadIdx.x;
    const int blk = blockIdx.x;        // node base = blk*16

    if (t < 128) {
        float s2 = ag[t] * rsqrtf(av[t] + 1e-5f);
        s_b2[t] = (attn_b[t] * s2 + ab[t] - am[t] * s2) * LOG2E;
        s_s2[t] = s2 * LOG2E;
    }
    __syncthreads();

    for (int idx = t; idx < 128*F_; idx += 256) {
        int c = idx / F_, f = idx % F_;
        s_wl[c*60 + f] = Wl[idx];
        s_ws[c*60 + f] = Ws[idx];
        s_wd[c*60 + f] = Wd[idx];
    }
    {
        const float4* aw4 = (const float4*)attn_w;
        for (int i4 = t; i4 < C_*C_/4; i4 += 256) {
            float4 w = aw4[i4];
            int c = i4 >> 5, k = (i4 & 31) * 4;
            float s2 = s_s2[c];
            float* dst = s_aw + c*132 + k;
            dst[0] = w.x*s2; dst[1] = w.y*s2; dst[2] = w.z*s2; dst[3] = w.w*s2;
        }
    }
    for (int idx = t; idx < 16*F_; idx += 256) {
        int n = idx / F_, f = idx % F_;
        s_x[n*64 + f] = x[blk*16*F_ + idx];
    }
    __syncthreads();

    // export this block's awfT column slice (c = blk)
    if (t < 128) g_awfT[t*C_ + blk] = s_aw[blk*132 + t];

    const int c = t & 127, g = t >> 7;

    float accv[8], accs[8], accd[8];
#pragma unroll
    for (int n = 0; n < 8; n++) { accv[n] = 0.f; accs[n] = 0.f; accd[n] = 0.f; }

    for (int f4 = 0; f4 < 56; f4 += 4) {
        float4 wl4 = *(const float4*)(s_wl + c*60 + f4);
        float4 ws4 = *(const float4*)(s_ws + c*60 + f4);
        float4 wd4 = *(const float4*)(s_wd + c*60 + f4);
#pragma unroll
        for (int n = 0; n < 8; n++) {
            float4 x4 = *(const float4*)(s_x + (g*8 + n)*64 + f4);
            accv[n] = fmaf(x4.x, wl4.x, fmaf(x4.y, wl4.y, fmaf(x4.z, wl4.z, fmaf(x4.w, wl4.w, accv[n]))));
            accs[n] = fmaf(x4.x, ws4.x, fmaf(x4.y, ws4.y, fmaf(x4.z, ws4.z, fmaf(x4.w, ws4.w, accs[n]))));
            accd[n] = fmaf(x4.x, wd4.x, fmaf(x4.y, wd4.y, fmaf(x4.z, wd4.z, fmaf(x4.w, wd4.w, accd[n]))));
        }
    }
#pragma unroll
    for (int f = 56; f < F_; f++) {
        float wl = s_wl[c*60 + f], ws = s_ws[c*60 + f], wd = s_wd[c*60 + f];
#pragma unroll
        for (int n = 0; n < 8; n++) {
            float xv = s_x[(g*8 + n)*64 + f];
            accv[n] = fmaf(xv, wl, accv[n]);
            accs[n] = fmaf(xv, ws, accs[n]);
            accd[n] = fmaf(xv, wd, accd[n]);
        }
    }
#pragma unroll
    for (int n = 0; n < 8; n++) {
        int node = g*8 + n;
        g_v[(blk*16 + node)*C_ + c] = accv[n];
        s_as[node*128 + c] = accs[n];
        s_ad[node*128 + c] = accd[n];
    }
    __syncthreads();

    float ts[8], td[8];
#pragma unroll
    for (int n = 0; n < 8; n++) { ts[n] = 0.f; td[n] = 0.f; }

    for (int k4 = 0; k4 < C_; k4 += 4) {
        float4 aw4 = *(const float4*)(s_aw + c*132 + k4);
#pragma unroll
        for (int n = 0; n < 8; n++) {
            float4 a4 = *(const float4*)(s_as + (g*8 + n)*128 + k4);
            float4 d4 = *(const float4*)(s_ad + (g*8 + n)*128 + k4);
            ts[n] = fmaf(a4.x, aw4.x, fmaf(a4.y, aw4.y, fmaf(a4.z, aw4.z, fmaf(a4.w, aw4.w, ts[n]))));
            td[n] = fmaf(d4.x, aw4.x, fmaf(d4.y, aw4.y, fmaf(d4.z, aw4.z, fmaf(d4.w, aw4.w, td[n]))));
        }
    }
    float b2 = s_b2[c];
#pragma unroll
    for (int n = 0; n < 8; n++) {
        int node = g*8 + n;
        g_tsrc[(blk*16 + node)*C_ + c] = ts[n];
        g_tdst[(blk*16 + node)*C_ + c] = td[n] + b2;
    }
}

// =====================================================================
// Kernel 2: fused attention. grid = 128 (16 receivers), block = 1024,
// 1 CTA/SM, 32 warps, 128-row tiles, 4d x 4r thread tile.
// =====================================================================
__global__ void __launch_bounds__(1024, 1)
main_kernel(const float* __restrict__ pos, const float* __restrict__ nrm,
            const float* __restrict__ rptr,
            const float* __restrict__ pos_w, const float* __restrict__ pos_b,
            const float* __restrict__ pg, const float* __restrict__ pb,
            const float* __restrict__ pm, const float* __restrict__ pv,
            float* __restrict__ out)
{
    extern __shared__ float sh[];
    float* s_awt  = sh;                     // [c][d]        16384 f
    float* s_dt   = s_awt + C_*C_;          // [c][TILE]     16384 f
    float* s_sc   = s_dt;                   // [row][d] alias
    float* s_relf = s_dt + C_*TILE;         // [TILE][9]      1152 f
    float* s_pw   = s_relf + TILE*9;        // [128][6]        768 f
    float* s_pb   = s_pw + C_*6;            //                 128 f
    float* s_td   = s_pb + C_;              // [ii][d]        2048 f
    float* s_posn = s_td + G_*C_;           // [j][3]          768 f
    float* s_geo  = s_posn + 256*3;         // [ii][6]          96 f
    int*   s_rows = (int*)(s_geo + G_*6);   // MAXROWS
    int*   s_mask = s_rows + MAXROWS;       // [16][8]
    int*   s_woff = s_mask + 128;           // [16][8]
    int*   s_roff = s_woff + 128;           // [17]

    const int blk = blockIdx.x;
    const int b  = blk >> 4;
    const int i0 = (blk & 15) * G_;
    const int t  = threadIdx.x;
    const int wd = t >> 5, ln = t & 31;

    // ---- stage constants ----
    {
        const float4* src = (const float4*)g_awfT;
        float4* dst = (float4*)s_awt;
        for (int i4 = t; i4 < C_*C_/4; i4 += 1024) dst[i4] = src[i4];
    }
    if (t < C_) {   // fold pos_nn BN inline
        float s1 = pg[t] * rsqrtf(pv[t] + 1e-5f);
        s_pb[t] = pos_b[t] * s1 + pb[t] - pm[t] * s1;
#pragma unroll
        for (int k = 0; k < 6; k++) s_pw[t*6 + k] = pos_w[t*6 + k] * s1;
    }
    for (int idx = t; idx < G_*C_; idx += 1024) {
        int ii = idx >> 7, dd = idx & 127;
        s_td[idx] = g_tdst[(b*N_ + i0 + ii)*C_ + dd];
    }
    if (t < 256) {
        const float* pj = pos + (b*N_ + t)*3;
        s_posn[t*3+0] = pj[0]; s_posn[t*3+1] = pj[1]; s_posn[t*3+2] = pj[2];
    }
    if (t < G_*6) {
        int ii = t / 6, k = t % 6;
        s_geo[t] = (k < 3) ? pos[(b*N_ + i0 + ii)*3 + k]
                           : nrm[(b*N_ + i0 + ii)*3 + (k - 3)];
    }
    __syncthreads();

    float rr;
    { int iv = *(const int*)rptr; rr = (iv > 0 && iv < 1000000) ? (float)iv : *rptr; }
    const float r2 = rr * rr;

    // ---- deterministic sorted compaction (threads 0..255 = candidate j) ----
    unsigned predbits = 0;
    if (t < 256) {
        float px = s_posn[t*3+0], py = s_posn[t*3+1], pz = s_posn[t*3+2];
#pragma unroll
        for (int ii = 0; ii < G_; ii++) {
            float dx = s_geo[ii*6+0] - px;
            float dy = s_geo[ii*6+1] - py;
            float dz = s_geo[ii*6+2] - pz;
            if (dx*dx + dy*dy + dz*dz <= r2) predbits |= (1u << ii);
        }
    }
    if (t < 256) {
#pragma unroll
        for (int ii = 0; ii < G_; ii++) {
            unsigned msk = __ballot_sync(0xFFFFFFFFu, (predbits >> ii) & 1u);
            if (ln == 0) s_mask[ii*8 + wd] = (int)msk;
        }
    }
    __syncthreads();

    if (t < 32) {
        int ii = ln;
        int cnt = 0;
        if (ii < 16)
            for (int w = 0; w < 8; w++) cnt += __popc((unsigned)s_mask[ii*8 + w]);
        int incl = cnt;
#pragma unroll
        for (int off = 1; off < 16; off <<= 1) {
            int v = __shfl_up_sync(0xFFFFFFFFu, incl, off);
            if (ln >= off) incl += v;
        }
        if (ii < 16) {
            int excl = incl - cnt;
            s_roff[ii] = excl < MAXROWS ? excl : MAXROWS;
            int run = excl;
            for (int w = 0; w < 8; w++) {
                s_woff[ii*8 + w] = run;
                run += __popc((unsigned)s_mask[ii*8 + w]);
            }
            if (ii == 15) s_roff[16] = run < MAXROWS ? run : MAXROWS;
        }
    }
    __syncthreads();

    if (t < 256) {
#pragma unroll
        for (int ii = 0; ii < G_; ii++) {
            if ((predbits >> ii) & 1u) {
                unsigned msk = (unsigned)s_mask[ii*8 + wd];
                int idx = s_woff[ii*8 + wd] + __popc(msk & ((1u << ln) - 1u));
                if (idx < MAXROWS) s_rows[idx] = t | (ii << 8);
            }
        }
    }
    __syncthreads();
    const int nrows = s_roff[16];
    const int T = (nrows + TILE - 1) & ~(TILE - 1);
    if (t < T - nrows) s_rows[nrows + t] = 0;   // benign padding
    __syncthreads();

    // ---- roles ----
    // matvec: warp = (dcol: w&3, rblk: w>>2); lane = (dg: ln&7, rg: ln>>3)
    const int dcol = wd & 3, rblk = wd >> 2;
    const int d0 = dcol*32 + (ln & 7)*4;
    const int r0 = rblk*16 + (ln >> 3)*4;
    // epilogue: (d, q): q handles receivers 2q, 2q+1
    const int d = t & 127, q = t >> 7;

    const float* tsb = g_tsrc + (size_t)(b*N_)*C_;
    const float* vb  = g_v    + (size_t)(b*N_)*C_;

    float l_[2] = {0.f, 0.f}, o_[2] = {0.f, 0.f};

    for (int base = 0; base < T; base += TILE) {
        // --- relative geometry for TILE rows ---
        if (t < TILE) {
            int tag = s_rows[base + t];
            int j = tag & 255, ii = tag >> 8;
            const float* nj = nrm + (b*N_ + j)*3;
            float* rf = s_relf + t*9;
            rf[0] = s_geo[ii*6+0] - s_posn[j*3+0];
            rf[1] = s_geo[ii*6+1] - s_posn[j*3+1];
            rf[2] = s_geo[ii*6+2] - s_posn[j*3+2];
            rf[3] = s_geo[ii*6+3] - nj[0];
            rf[4] = s_geo[ii*6+4] - nj[1];
            rf[5] = s_geo[ii*6+5] - nj[2];
        }
        __syncthreads();

        // --- delta fill: s_dt[c][row], row = t&127, c-chunk = t>>7 (16 c) ---
        {
            int row = t & 127, cg = t >> 7;
            float rf[6];
#pragma unroll
            for (int k = 0; k < 6; k++) rf[k] = s_relf[row*9 + k];
#pragma unroll
            for (int cc = 0; cc < 16; cc++) {
                int c = cg*16 + cc;
                float dv = s_pb[c];
#pragma unroll
                for (int k = 0; k < 6; k++) dv = fmaf(rf[k], s_pw[c*6 + k], dv);
                s_dt[c*TILE + row] = fmaxf(dv, 0.f);
            }
        }
        __syncthreads();

        // --- matvec: 4 d x 4 rows per thread ---
        unsigned long long acc[4][2];
#pragma unroll
        for (int r = 0; r < 4; r++) { acc[r][0] = 0ULL; acc[r][1] = 0ULL; }

#pragma unroll 2
        for (int c = 0; c < C_; c++) {
            ulonglong2 wa = *(const ulonglong2*)(s_awt + c*C_ + d0);   // 2 d-pairs
            float4 rv = *(const float4*)(s_dt + c*TILE + r0);          // 4 rows
            unsigned long long b0 = dup2(rv.x), b1 = dup2(rv.y);
            unsigned long long b2v = dup2(rv.z), b3 = dup2(rv.w);
            fma2(acc[0][0], wa.x, b0);  fma2(acc[0][1], wa.y, b0);
            fma2(acc[1][0], wa.x, b1);  fma2(acc[1][1], wa.y, b1);
            fma2(acc[2][0], wa.x, b2v); fma2(acc[2][1], wa.y, b2v);
            fma2(acc[3][0], wa.x, b3);  fma2(acc[3][1], wa.y, b3);
        }
        __syncthreads();   // all s_dt reads done before s_sc overwrite (alias)

#pragma unroll
        for (int r = 0; r < 4; r++) {
            *(unsigned long long*)(s_sc + (r0 + r)*C_ + d0)     = acc[r][0];
            *(unsigned long long*)(s_sc + (r0 + r)*C_ + d0 + 2) = acc[r][1];
        }
        __syncthreads();

        // --- merged epilogue: gather + exp2 softmax accumulation ---
        float pwd[6];
#pragma unroll
        for (int k = 0; k < 6; k++) pwd[k] = s_pw[d*6 + k];
        const float pbd = s_pb[d];
#pragma unroll
        for (int s = 0; s < 2; s++) {
            int ii = q*2 + s;
            int lo = s_roff[ii]   - base; if (lo < 0)    lo = 0;
            int hi = s_roff[ii+1] - base; if (hi > TILE) hi = TILE;
            const float tdv = s_td[ii*C_ + d];
#pragma unroll 2
            for (int r = lo; r < hi; r++) {
                int j = s_rows[base + r] & 255;
                float tsv = tsb[j*C_ + d];
                float vvv = vb[j*C_ + d];
                float z = s_sc[r*C_ + d] + tdv - tsv;
                float sv = fmaxf(z, 0.f);
                float e = exp2f(sv);
                float dv = pbd;
#pragma unroll
                for (int kk = 0; kk < 6; kk++)
                    dv = fmaf(s_relf[r*9 + kk], pwd[kk], dv);
                dv = fmaxf(dv, 0.f);
                l_[s] += e;
                o_[s] = fmaf(e, vvv + dv, o_[s]);
            }
        }
        __syncthreads();
    }

#pragma unroll
    for (int s = 0; s < 2; s++) {
        int ii = q*2 + s;
        out[(b*N_ + i0 + ii)*C_ + d] = o_[s] / l_[s];   // self-loop => l > 0
    }
}

// ---------------- launch ----------------
extern "C" void kernel_launch(void* const* d_in, const int* in_sizes, int n_in,
                              void* d_out, int out_size)
{
    const float* x      = (const float*)d_in[0];
    const float* pos    = (const float*)d_in[1];
    const float* normal = (const float*)d_in[2];
    const float* W_lin  = (const float*)d_in[3];
    const float* W_src  = (const float*)d_in[4];
    const float* W_dst  = (const float*)d_in[5];
    const float* pos_w  = (const float*)d_in[6];
    const float* pos_b  = (const float*)d_in[7];
    const float* pbn_g  = (const float*)d_in[8];
    const float* pbn_b  = (const float*)d_in[9];
    const float* pbn_m  = (const float*)d_in[10];
    const float* pbn_v  = (const float*)d_in[11];
    const float* attn_w = (const float*)d_in[12];
    const float* attn_b = (const float*)d_in[13];
    const float* abn_g  = (const float*)d_in[14];
    const float* abn_b  = (const float*)d_in[15];
    const float* abn_m  = (const float*)d_in[16];
    const float* abn_v  = (const float*)d_in[17];
    const float* rptr   = (const float*)d_in[18];
    float* out = (float*)d_out;

    const size_t smemB = (size_t)(3*128*60 + 128*132 + 16*64 + 2*16*128 + 256) * sizeof(float);
    const size_t smemC = (size_t)(C_*C_ + C_*TILE + TILE*9 + C_*6 + C_ + G_*C_ + 256*3 + G_*6) * sizeof(float)
                       + (size_t)(MAXROWS + 128 + 128 + 17) * sizeof(int);

    cudaFuncSetAttribute(precompute_kernel, cudaFuncAttributeMaxDynamicSharedMemorySize, (int)smemB);
    cudaFuncSetAttribute(main_kernel,       cudaFuncAttributeMaxDynamicSharedMemorySize, (int)smemC);
    (void)in_sizes; (void)n_in; (void)out_size;

    precompute_kernel<<<B_*N_/16, 256, smemB>>>(x, W_lin, W_src, W_dst,
                                                attn_w, attn_b, abn_g, abn_b, abn_m, abn_v);
    main_kernel<<<B_*N_/G_, 1024, smemC>>>(pos, normal, rptr,
                                           pos_w, pos_b, pbn_g, pbn_b, pbn_m, pbn_v,
                                           out);
}

// round 8
// speedup vs baseline: 1.7410x; 1.3317x over previous
#include <cuda_runtime.h>
#include <cuda_bf16.h>
#include <math.h>
#include <stdint.h>

#define B_ 8
#define N_ 256
#define F_ 59
#define C_ 128
#define G_ 16           // receivers per main block
#define TILE 128        // rows per tile
#define MAXROWS 768
#define LOG2E 1.4426950408889634f
#define AS 136          // bf16 elems per padded row (A and W tiles)
#define SCS 132         // f32 elems per padded score row

// ---------------- device scratch ----------------
__device__ float g_v[B_*N_*C_];
__device__ float g_tsrc[B_*N_*C_];
__device__ float g_tdst[B_*N_*C_];
__device__ __nv_bfloat16 g_awhi[C_*C_];  // folded attn_w*log2e, [d][c], hi
__device__ __nv_bfloat16 g_awlo[C_*C_];  // lo residual

// ---------------- smem byte offsets (main kernel) ----------------
#define OFF_AHI   0          // delta hi bf16 [128][AS] = 34816 B
#define OFF_ALO   34816      // delta lo bf16            34816 B
#define OFF_SC    0          // f32 scores [128][SCS] = 67584 B (ALIAS of A tiles)
#define OFF_WHI   69632      // weights hi bf16 [128][AS]
#define OFF_WLO   104448     // weights lo
#define OFF_RELF  139264     // [128][9] f32 = 4608
#define OFF_PW    143872     // [128][6] f32 = 3072
#define OFF_PB    146944     // [128] f32 = 512
#define OFF_TD    147456     // [16][128] f32 = 8192
#define OFF_POSN  155648     // [256][3] f32 = 3072
#define OFF_GEO   158720     // [16][6] f32 = 384
#define OFF_ROWS  159104     // int[768] = 3072
#define OFF_MASK  162176     // int[128] = 512
#define OFF_WOFF  162688     // int[128] = 512
#define OFF_ROFF  163200     // int[17] = 68 -> pad
#define SMEM_MAIN 163328

static __device__ __forceinline__ uint32_t smem_u32(const void* p) {
    uint32_t a;
    asm("{ .reg .u64 t; cvta.to.shared.u64 t, %1; cvt.u32.u64 %0, t; }" : "=r"(a) : "l"(p));
    return a;
}

#define LDM4(r, addr) \
    asm volatile("ldmatrix.sync.aligned.m8n8.x4.shared.b16 {%0,%1,%2,%3}, [%4];" \
        : "=r"((r)[0]), "=r"((r)[1]), "=r"((r)[2]), "=r"((r)[3]) : "r"(addr))

#define MMA_BF16(c, a, b0, b1) \
    asm volatile("mma.sync.aligned.m16n8k16.row.col.f32.bf16.bf16.f32 " \
        "{%0,%1,%2,%3}, {%4,%5,%6,%7}, {%8,%9}, {%0,%1,%2,%3};" \
        : "+f"((c)[0]), "+f"((c)[1]), "+f"((c)[2]), "+f"((c)[3]) \
        : "r"((a)[0]), "r"((a)[1]), "r"((a)[2]), "r"((a)[3]), "r"(b0), "r"(b1))

// =====================================================================
// Kernel 1: per-node precompute (+ BN fold, bf16 hi/lo weight export)
// grid = 128 (16 nodes each), block = 256
// =====================================================================
__global__ void __launch_bounds__(256, 1)
precompute_kernel(const float* __restrict__ x,
                  const float* __restrict__ Wl,
                  const float* __restrict__ Ws,
                  const float* __restrict__ Wd,
                  const float* __restrict__ attn_w, const float* __restrict__ attn_b,
                  const float* __restrict__ ag, const float* __restrict__ ab,
                  const float* __restrict__ am, const float* __restrict__ av)
{
    extern __shared__ float sh[];
    float* s_wl = sh;                  // [128][60]
    float* s_ws = s_wl + 128*60;
    float* s_wd = s_ws + 128*60;
    float* s_aw = s_wd + 128*60;       // [128][132] folded (x log2e)
    float* s_x  = s_aw + 128*132;      // [16][64]
    float* s_as = s_x  + 16*64;        // [16][128]
    float* s_ad = s_as + 16*128;       // [16][128]
    float* s_s2 = s_ad + 16*128;       // [128]
    float* s_b2 = s_s2 + 128;          // [128]

    const int t   = threadIdx.x;
    const int blk = blockIdx.x;

    if (t < 128) {
        float s2 = ag[t] * rsqrtf(av[t] + 1e-5f);
        s_b2[t] = (attn_b[t] * s2 + ab[t] - am[t] * s2) * LOG2E;
        s_s2[t] = s2 * LOG2E;
    }
    __syncthreads();

    for (int idx = t; idx < 128*F_; idx += 256) {
        int c = idx / F_, f = idx % F_;
        s_wl[c*60 + f] = Wl[idx];
        s_ws[c*60 + f] = Ws[idx];
        s_wd[c*60 + f] = Wd[idx];
    }
    {
        const float4* aw4 = (const float4*)attn_w;
        for (int i4 = t; i4 < C_*C_/4; i4 += 256) {
            float4 w = aw4[i4];
            int c = i4 >> 5, k = (i4 & 31) * 4;
            float s2 = s_s2[c];
            float* dst = s_aw + c*132 + k;
            dst[0] = w.x*s2; dst[1] = w.y*s2; dst[2] = w.z*s2; dst[3] = w.w*s2;
        }
    }
    for (int idx = t; idx < 16*F_; idx += 256) {
        int n = idx / F_, f = idx % F_;
        s_x[n*64 + f] = x[blk*16*F_ + idx];
    }
    __syncthreads();

    // block 0 exports bf16 hi/lo split of folded attn weights ([d][c])
    if (blk == 0) {
        for (int idx = t; idx < C_*C_; idx += 256) {
            float w = s_aw[(idx >> 7)*132 + (idx & 127)];
            __nv_bfloat16 h = __float2bfloat16(w);
            g_awhi[idx] = h;
            g_awlo[idx] = __float2bfloat16(w - __bfloat162float(h));
        }
    }

    const int c = t & 127, g = t >> 7;

    float accv[8], accs[8], accd[8];
#pragma unroll
    for (int n = 0; n < 8; n++) { accv[n] = 0.f; accs[n] = 0.f; accd[n] = 0.f; }

    for (int f4 = 0; f4 < 56; f4 += 4) {
        float4 wl4 = *(const float4*)(s_wl + c*60 + f4);
        float4 ws4 = *(const float4*)(s_ws + c*60 + f4);
        float4 wd4 = *(const float4*)(s_wd + c*60 + f4);
#pragma unroll
        for (int n = 0; n < 8; n++) {
            float4 x4 = *(const float4*)(s_x + (g*8 + n)*64 + f4);
            accv[n] = fmaf(x4.x, wl4.x, fmaf(x4.y, wl4.y, fmaf(x4.z, wl4.z, fmaf(x4.w, wl4.w, accv[n]))));
            accs[n] = fmaf(x4.x, ws4.x, fmaf(x4.y, ws4.y, fmaf(x4.z, ws4.z, fmaf(x4.w, ws4.w, accs[n]))));
            accd[n] = fmaf(x4.x, wd4.x, fmaf(x4.y, wd4.y, fmaf(x4.z, wd4.z, fmaf(x4.w, wd4.w, accd[n]))));
        }
    }
#pragma unroll
    for (int f = 56; f < F_; f++) {
        float wl = s_wl[c*60 + f], ws = s_ws[c*60 + f], wd = s_wd[c*60 + f];
#pragma unroll
        for (int n = 0; n < 8; n++) {
            float xv = s_x[(g*8 + n)*64 + f];
            accv[n] = fmaf(xv, wl, accv[n]);
            accs[n] = fmaf(xv, ws, accs[n]);
            accd[n] = fmaf(xv, wd, accd[n]);
        }
    }
#pragma unroll
    for (int n = 0; n < 8; n++) {
        int node = g*8 + n;
        g_v[(blk*16 + node)*C_ + c] = accv[n];
        s_as[node*128 + c] = accs[n];
        s_ad[node*128 + c] = accd[n];
    }
    __syncthreads();

    float ts[8], td[8];
#pragma unroll
    for (int n = 0; n < 8; n++) { ts[n] = 0.f; td[n] = 0.f; }

    for (int k4 = 0; k4 < C_; k4 += 4) {
        float4 aw4 = *(const float4*)(s_aw + c*132 + k4);
#pragma unroll
        for (int n = 0; n < 8; n++) {
            float4 a4 = *(const float4*)(s_as + (g*8 + n)*128 + k4);
            float4 d4 = *(const float4*)(s_ad + (g*8 + n)*128 + k4);
            ts[n] = fmaf(a4.x, aw4.x, fmaf(a4.y, aw4.y, fmaf(a4.z, aw4.z, fmaf(a4.w, aw4.w, ts[n]))));
            td[n] = fmaf(d4.x, aw4.x, fmaf(d4.y, aw4.y, fmaf(d4.z, aw4.z, fmaf(d4.w, aw4.w, td[n]))));
        }
    }
    float b2 = s_b2[c];
#pragma unroll
    for (int n = 0; n < 8; n++) {
        int node = g*8 + n;
        g_tsrc[(blk*16 + node)*C_ + c] = ts[n];
        g_tdst[(blk*16 + node)*C_ + c] = td[n] + b2;
    }
}

// =====================================================================
// Kernel 2: fused attention, mma.sync (HMMA) score GEMM, bf16 hi/lo.
// grid = 128 (16 receivers), block = 1024.
// =====================================================================
__global__ void __launch_bounds__(1024, 1)
main_kernel(const float* __restrict__ pos, const float* __restrict__ nrm,
            const float* __restrict__ rptr,
            const float* __restrict__ pos_w, const float* __restrict__ pos_b,
            const float* __restrict__ pg, const float* __restrict__ pb,
            const float* __restrict__ pm, const float* __restrict__ pv,
            float* __restrict__ out)
{
    extern __shared__ char smem[];
    const uint32_t sb = smem_u32(smem);

    float* s_relf = (float*)(smem + OFF_RELF);
    float* s_pw   = (float*)(smem + OFF_PW);
    float* s_pb   = (float*)(smem + OFF_PB);
    float* s_td   = (float*)(smem + OFF_TD);
    float* s_posn = (float*)(smem + OFF_POSN);
    float* s_geo  = (float*)(smem + OFF_GEO);
    float* s_sc   = (float*)(smem + OFF_SC);
    int*   s_rows = (int*)(smem + OFF_ROWS);
    int*   s_mask = (int*)(smem + OFF_MASK);
    int*   s_woff = (int*)(smem + OFF_WOFF);
    int*   s_roff = (int*)(smem + OFF_ROFF);

    const int blk = blockIdx.x;
    const int b  = blk >> 4;
    const int i0 = (blk & 15) * G_;
    const int t  = threadIdx.x;
    const int wd = t >> 5, ln = t & 31;

    // ---- stage constants ----
    {   // weights hi/lo bf16 -> padded [d][AS] tiles
        const uint4* srh = (const uint4*)g_awhi;
        const uint4* srl = (const uint4*)g_awlo;
        for (int i4 = t; i4 < C_*C_/8; i4 += 1024) {
            int e = i4 * 8, dd = e >> 7, c0 = e & 127;
            int off = (dd*AS + c0) * 2;
            *(uint4*)(smem + OFF_WHI + off) = srh[i4];
            *(uint4*)(smem + OFF_WLO + off) = srl[i4];
        }
    }
    if (t < C_) {   // fold pos_nn BN inline
        float s1 = pg[t] * rsqrtf(pv[t] + 1e-5f);
        s_pb[t] = pos_b[t] * s1 + pb[t] - pm[t] * s1;
#pragma unroll
        for (int k = 0; k < 6; k++) s_pw[t*6 + k] = pos_w[t*6 + k] * s1;
    }
    for (int idx = t; idx < G_*C_; idx += 1024) {
        int ii = idx >> 7, dd = idx & 127;
        s_td[idx] = g_tdst[(b*N_ + i0 + ii)*C_ + dd];
    }
    if (t < 256) {
        const float* pj = pos + (b*N_ + t)*3;
        s_posn[t*3+0] = pj[0]; s_posn[t*3+1] = pj[1]; s_posn[t*3+2] = pj[2];
    }
    if (t < G_*6) {
        int ii = t / 6, k = t % 6;
        s_geo[t] = (k < 3) ? pos[(b*N_ + i0 + ii)*3 + k]
                           : nrm[(b*N_ + i0 + ii)*3 + (k - 3)];
    }
    __syncthreads();

    float rr;
    { int iv = *(const int*)rptr; rr = (iv > 0 && iv < 1000000) ? (float)iv : *rptr; }
    const float r2 = rr * rr;

    // ---- deterministic sorted compaction (threads 0..255 = candidate j) ----
    unsigned predbits = 0;
    if (t < 256) {
        float px = s_posn[t*3+0], py = s_posn[t*3+1], pz = s_posn[t*3+2];
#pragma unroll
        for (int ii = 0; ii < G_; ii++) {
            float dx = s_geo[ii*6+0] - px;
            float dy = s_geo[ii*6+1] - py;
            float dz = s_geo[ii*6+2] - pz;
            if (dx*dx + dy*dy + dz*dz <= r2) predbits |= (1u << ii);
        }
#pragma unroll
        for (int ii = 0; ii < G_; ii++) {
            unsigned msk = __ballot_sync(0xFFFFFFFFu, (predbits >> ii) & 1u);
            if (ln == 0) s_mask[ii*8 + wd] = (int)msk;
        }
    }
    __syncthreads();

    if (t < 32) {
        int ii = ln;
        int cnt = 0;
        if (ii < 16)
            for (int w = 0; w < 8; w++) cnt += __popc((unsigned)s_mask[ii*8 + w]);
        int incl = cnt;
#pragma unroll
        for (int off = 1; off < 16; off <<= 1) {
            int v = __shfl_up_sync(0xFFFFFFFFu, incl, off);
            if (ln >= off) incl += v;
        }
        if (ii < 16) {
            int excl = incl - cnt;
            s_roff[ii] = excl < MAXROWS ? excl : MAXROWS;
            int run = excl;
            for (int w = 0; w < 8; w++) {
                s_woff[ii*8 + w] = run;
                run += __popc((unsigned)s_mask[ii*8 + w]);
            }
            if (ii == 15) s_roff[16] = run < MAXROWS ? run : MAXROWS;
        }
    }
    __syncthreads();

    if (t < 256) {
#pragma unroll
        for (int ii = 0; ii < G_; ii++) {
            if ((predbits >> ii) & 1u) {
                unsigned msk = (unsigned)s_mask[ii*8 + wd];
                int idx = s_woff[ii*8 + wd] + __popc(msk & ((1u << ln) - 1u));
                if (idx < MAXROWS) s_rows[idx] = t | (ii << 8);
            }
        }
    }
    __syncthreads();
    const int nrows = s_roff[16];
    const int T = (nrows + TILE - 1) & ~(TILE - 1);
    if (t < T - nrows) s_rows[nrows + t] = 0;   // benign padding
    __syncthreads();

    // ---- roles ----
    const int d = t & 127, q = t >> 7;   // epilogue: channel, receiver-pair group
    const int mt = wd & 7;               // MMA: m-tile (rows mt*16..+15)
    const int nb = wd >> 3;              // MMA: n-block (cols nb*32..+31)

    // ldmatrix lane addresses (k-offset added per step)
    const int lrow = ln & 15;
    const int lkof = (ln >> 4) * 8;
    const uint32_t aHi0 = sb + OFF_AHI + ((mt*16 + lrow)*AS + lkof)*2;
    const uint32_t aLo0 = aHi0 + (OFF_ALO - OFF_AHI);
    const uint32_t bHi0 = sb + OFF_WHI + ((nb*32 + lrow)*AS + lkof)*2;
    const uint32_t bHi1 = bHi0 + 16*AS*2;
    const uint32_t bLo0 = bHi0 + (OFF_WLO - OFF_WHI);
    const uint32_t bLo1 = bHi1 + (OFF_WLO - OFF_WHI);

    const float* tsb = g_tsrc + (size_t)(b*N_)*C_;
    const float* vb  = g_v    + (size_t)(b*N_)*C_;

    float pwd[6];
#pragma unroll
    for (int k = 0; k < 6; k++) pwd[k] = s_pw[d*6 + k];
    const float pbd = s_pb[d];

    float l_[2] = {0.f, 0.f}, o_[2] = {0.f, 0.f};

    for (int base = 0; base < T; base += TILE) {
        // --- relative geometry for TILE rows ---
        if (t < TILE) {
            int tag = s_rows[base + t];
            int j = tag & 255, ii = tag >> 8;
            const float* nj = nrm + (b*N_ + j)*3;
            float* rf = s_relf + t*9;
            rf[0] = s_geo[ii*6+0] - s_posn[j*3+0];
            rf[1] = s_geo[ii*6+1] - s_posn[j*3+1];
            rf[2] = s_geo[ii*6+2] - s_posn[j*3+2];
            rf[3] = s_geo[ii*6+3] - nj[0];
            rf[4] = s_geo[ii*6+4] - nj[1];
            rf[5] = s_geo[ii*6+5] - nj[2];
        }
        __syncthreads();

        // --- delta fill: bf16 hi/lo split, row = t&127, 16 c per thread ---
        {
            int row = t & 127, cg = t >> 7;
            int c0 = cg*16;
            float rf[6];
#pragma unroll
            for (int k = 0; k < 6; k++) rf[k] = s_relf[row*9 + k];
            float dv[16];
#pragma unroll
            for (int cc = 0; cc < 16; cc++) {
                int c = c0 + cc;
                float v = s_pb[c];
#pragma unroll
                for (int k = 0; k < 6; k++) v = fmaf(rf[k], s_pw[c*6 + k], v);
                dv[cc] = fmaxf(v, 0.f);
            }
            unsigned ph[8], pl[8];
#pragma unroll
            for (int p = 0; p < 8; p++) {
                __nv_bfloat162 h2 = __floats2bfloat162_rn(dv[2*p], dv[2*p+1]);
                float q0 = dv[2*p]   - __bfloat162float(h2.x);
                float q1 = dv[2*p+1] - __bfloat162float(h2.y);
                __nv_bfloat162 l2 = __floats2bfloat162_rn(q0, q1);
                ph[p] = *(unsigned*)&h2;
                pl[p] = *(unsigned*)&l2;
            }
            int off = (row*AS + c0)*2;
            *(uint4*)(smem + OFF_AHI + off)      = make_uint4(ph[0], ph[1], ph[2], ph[3]);
            *(uint4*)(smem + OFF_AHI + off + 16) = make_uint4(ph[4], ph[5], ph[6], ph[7]);
            *(uint4*)(smem + OFF_ALO + off)      = make_uint4(pl[0], pl[1], pl[2], pl[3]);
            *(uint4*)(smem + OFF_ALO + off + 16) = make_uint4(pl[4], pl[5], pl[6], pl[7]);
        }
        __syncthreads();

        // --- tensor-core score GEMM: 3-way bf16 split ---
        float acc[4][4];
#pragma unroll
        for (int tn = 0; tn < 4; tn++)
#pragma unroll
            for (int i = 0; i < 4; i++) acc[tn][i] = 0.f;

#pragma unroll
        for (int kk = 0; kk < 8; kk++) {
            const uint32_t ko = kk * 32;   // 16 bf16 = 32 bytes
            uint32_t ah[4], al[4], bh0[4], bh1[4], bl0[4], bl1[4];
            LDM4(ah,  aHi0 + ko);
            LDM4(al,  aLo0 + ko);
            LDM4(bh0, bHi0 + ko);
            LDM4(bh1, bHi1 + ko);
            LDM4(bl0, bLo0 + ko);
            LDM4(bl1, bLo1 + ko);
            // n-tiles: 0:{bh0[0],bh0[2]} 1:{bh0[1],bh0[3]} 2:{bh1[0],bh1[2]} 3:{bh1[1],bh1[3]}
            MMA_BF16(acc[0], ah, bh0[0], bh0[2]);
            MMA_BF16(acc[1], ah, bh0[1], bh0[3]);
            MMA_BF16(acc[2], ah, bh1[0], bh1[2]);
            MMA_BF16(acc[3], ah, bh1[1], bh1[3]);
            MMA_BF16(acc[0], ah, bl0[0], bl0[2]);
            MMA_BF16(acc[1], ah, bl0[1], bl0[3]);
            MMA_BF16(acc[2], ah, bl1[0], bl1[2]);
            MMA_BF16(acc[3], ah, bl1[1], bl1[3]);
            MMA_BF16(acc[0], al, bh0[0], bh0[2]);
            MMA_BF16(acc[1], al, bh0[1], bh0[3]);
            MMA_BF16(acc[2], al, bh1[0], bh1[2]);
            MMA_BF16(acc[3], al, bh1[1], bh1[3]);
        }
        __syncthreads();   // all A reads done before score overwrite (alias)

        // --- store score frags: thread (g=ln>>2, tq=ln&3) ---
        {
            int gid = ln >> 2, tq = ln & 3;
            int row0 = mt*16 + gid;
#pragma unroll
            for (int tn = 0; tn < 4; tn++) {
                int col = nb*32 + tn*8 + tq*2;
                *(float2*)(s_sc + row0*SCS + col)       = make_float2(acc[tn][0], acc[tn][1]);
                *(float2*)(s_sc + (row0+8)*SCS + col)   = make_float2(acc[tn][2], acc[tn][3]);
            }
        }
        __syncthreads();

        // --- merged epilogue: gather + exp2 softmax accumulation ---
#pragma unroll
        for (int s = 0; s < 2; s++) {
            int ii = q*2 + s;
            int lo = s_roff[ii]   - base; if (lo < 0)    lo = 0;
            int hi = s_roff[ii+1] - base; if (hi > TILE) hi = TILE;
            const float tdv = s_td[ii*C_ + d];
#pragma unroll 2
            for (int r = lo; r < hi; r++) {
                int j = s_rows[base + r] & 255;
                float tsv = tsb[j*C_ + d];
                float vvv = vb[j*C_ + d];
                float z = s_sc[r*SCS + d] + tdv - tsv;
                float sv = fmaxf(z, 0.f);
                float e = exp2f(sv);
                float dvv = pbd;
#pragma unroll
                for (int kk = 0; kk < 6; kk++)
                    dvv = fmaf(s_relf[r*9 + kk], pwd[kk], dvv);
                dvv = fmaxf(dvv, 0.f);
                l_[s] += e;
                o_[s] = fmaf(e, vvv + dvv, o_[s]);
            }
        }
        __syncthreads();
    }

#pragma unroll
    for (int s = 0; s < 2; s++) {
        int ii = q*2 + s;
        out[(b*N_ + i0 + ii)*C_ + d] = o_[s] / l_[s];   // self-loop => l > 0
    }
}

// ---------------- launch ----------------
extern "C" void kernel_launch(void* const* d_in, const int* in_sizes, int n_in,
                              void* d_out, int out_size)
{
    const float* x      = (const float*)d_in[0];
    const float* pos    = (const float*)d_in[1];
    const float* normal = (const float*)d_in[2];
    const float* W_lin  = (const float*)d_in[3];
    const float* W_src  = (const float*)d_in[4];
    const float* W_dst  = (const float*)d_in[5];
    const float* pos_w  = (const float*)d_in[6];
    const float* pos_b  = (const float*)d_in[7];
    const float* pbn_g  = (const float*)d_in[8];
    const float* pbn_b  = (const float*)d_in[9];
    const float* pbn_m  = (const float*)d_in[10];
    const float* pbn_v  = (const float*)d_in[11];
    const float* attn_w = (const float*)d_in[12];
    const float* attn_b = (const float*)d_in[13];
    const float* abn_g  = (const float*)d_in[14];
    const float* abn_b  = (const float*)d_in[15];
    const float* abn_m  = (const float*)d_in[16];
    const float* abn_v  = (const float*)d_in[17];
    const float* rptr   = (const float*)d_in[18];
    float* out = (float*)d_out;

    const size_t smemB = (size_t)(3*128*60 + 128*132 + 16*64 + 2*16*128 + 256) * sizeof(float);

    cudaFuncSetAttribute(precompute_kernel, cudaFuncAttributeMaxDynamicSharedMemorySize, (int)smemB);
    cudaFuncSetAttribute(main_kernel,       cudaFuncAttributeMaxDynamicSharedMemorySize, SMEM_MAIN);
    (void)in_sizes; (void)n_in; (void)out_size;

    precompute_kernel<<<B_*N_/16, 256, smemB>>>(x, W_lin, W_src, W_dst,
                                                attn_w, attn_b, abn_g, abn_b, abn_m, abn_v);
    main_kernel<<<B_*N_/G_, 1024, SMEM_MAIN>>>(pos, normal, rptr,
                                               pos_w, pos_b, pbn_g, pbn_b, pbn_m, pbn_v,
                                               out);
}